// round 6
// baseline (speedup 1.0000x reference)
#include <cuda_runtime.h>
#include <cstdint>

// DETR-style postprocess:
//   logits [256,1000,80] f32, boxes [256,1000,4] f32 (cxcywh)
//   -> labels [256,300], boxes_xyxy [256,300,4], scores [256,300]
// Output concatenated flat f32: labels | boxes | scores. (verified R3)

#define BATCH      256
#define QQ         1000
#define CC         80
#define NELEM      80000      // QQ*CC per batch
#define NV4        20000      // NELEM/4
#define KTOP       300
#define CAP        4096
#define NBINS      2048
#define T_STATIC   2.5f

#define BPB        8          // filter blocks per batch
#define FTHREADS   256
#define CHUNK      (NV4 / BPB)                       // 2500 float4 per filter block
#define FITERS     ((CHUNK + FTHREADS - 1) / FTHREADS)  // 10

#define RTHREADS   512

#define LBL_OFF    0
#define BOX_OFF    (BATCH * KTOP)            // 76800
#define SCR_OFF    (BATCH * KTOP * 5)        // 384000

// Global scratch (no allocation allowed; __device__ globals are zero-init at load)
__device__ unsigned long long g_pack[BATCH][CAP];
__device__ int g_cnt[BATCH];

// Monotone float->uint key (ascending order preserved)
__device__ __forceinline__ unsigned f2key(float x) {
    unsigned b = __float_as_uint(x);
    return (b & 0x80000000u) ? ~b : (b | 0x80000000u);
}
__device__ __forceinline__ float key2f(unsigned k) {
    unsigned b = (k & 0x80000000u) ? (k & 0x7FFFFFFFu) : ~k;
    return __uint_as_float(b);
}

// ------------------------------------------------------------------
// Kernel 1: stream logits, warp-aggregated candidate push (>T) to global
// ------------------------------------------------------------------
__global__ __launch_bounds__(FTHREADS, 8)
void filter_kernel(const float* __restrict__ logits)
{
    const int b    = blockIdx.y;
    const int base = blockIdx.x * CHUNK;
    const int lane = threadIdx.x & 31;
    const float4* lg4 = (const float4*)(logits + (size_t)b * NELEM);

    #pragma unroll
    for (int it = 0; it < FITERS; it++) {
        int i = base + it * FTHREADS + threadIdx.x;
        bool inb = (i < base + CHUNK);
        float4 v;
        if (inb) v = lg4[i];
        else     v = make_float4(-1e30f, -1e30f, -1e30f, -1e30f);

        float vv[4] = {v.x, v.y, v.z, v.w};
        #pragma unroll
        for (int j = 0; j < 4; j++) {
            bool p = vv[j] > T_STATIC;
            unsigned mask = __ballot_sync(0xFFFFFFFFu, p);
            if (mask) {
                int nm  = __popc(mask);
                int ldr = __ffs(mask) - 1;
                int bp = 0;
                if (lane == ldr) bp = atomicAdd(&g_cnt[b], nm);
                bp = __shfl_sync(0xFFFFFFFFu, bp, ldr);
                if (p) {
                    int pos = bp + __popc(mask & ((1u << lane) - 1u));
                    if (pos < CAP) {
                        unsigned idx = (unsigned)(i * 4 + j);
                        g_pack[b][pos] = ((unsigned long long)f2key(vv[j]) << 32)
                                         | (unsigned long long)(~idx);
                    }
                }
            }
        }
    }
}

// ------------------------------------------------------------------
// Kernel 2: per-batch exact rank of candidates + output (+exact fallback)
// ------------------------------------------------------------------
__global__ __launch_bounds__(RTHREADS)
void rank_kernel(const float* __restrict__ logits,
                 const float* __restrict__ boxes,
                 float* __restrict__ out)
{
    __shared__ unsigned long long s_pack[CAP];
    __shared__ unsigned s_hist[NBINS];   // fallback only
    __shared__ int s_cnt;
    __shared__ int s_b1, s_gt, s_b2;

    const int b   = blockIdx.x;
    const int tid = threadIdx.x;
    const float4* lg4 = (const float4*)(logits + (size_t)b * NELEM);

    int M = g_cnt[b];
    int Mc = min(M, CAP);

    // copy candidates global -> shared
    for (int i = tid; i < Mc; i += RTHREADS)
        s_pack[i] = g_pack[b][i];

    // reset counter for the next graph replay
    if (tid == 0) g_cnt[b] = 0;
    __syncthreads();

    // ---------- Fallback: exact 2-level radix select (statistically never) ----------
    if (M < KTOP || M > CAP) {
        for (int i = tid; i < NBINS; i += RTHREADS) s_hist[i] = 0;
        __syncthreads();
        for (int i = tid; i < NV4; i += RTHREADS) {
            float4 v = lg4[i];
            float vv[4] = {v.x, v.y, v.z, v.w};
            #pragma unroll
            for (int j = 0; j < 4; j++)
                atomicAdd(&s_hist[f2key(vv[j]) >> 21], 1u);
        }
        __syncthreads();
        if (tid == 0) {
            int acc = 0, b1 = 0;
            for (int bin = NBINS - 1; bin >= 0; bin--) {
                int c = (int)s_hist[bin];
                if (acc + c >= KTOP) { b1 = bin; break; }
                acc += c;
            }
            s_b1 = b1; s_gt = acc;
        }
        __syncthreads();
        const int b1 = s_b1;
        const int cnt_ge = s_gt + (int)s_hist[b1];

        if (cnt_ge <= CAP) {
            if (tid == 0) s_cnt = 0;
            __syncthreads();
            for (int i = tid; i < NV4; i += RTHREADS) {
                float4 v = lg4[i];
                float vv[4] = {v.x, v.y, v.z, v.w};
                #pragma unroll
                for (int j = 0; j < 4; j++) {
                    unsigned key = f2key(vv[j]);
                    if ((int)(key >> 21) >= b1) {
                        int pos = atomicAdd(&s_cnt, 1);
                        unsigned idx = (unsigned)(i * 4 + j);
                        s_pack[pos] = ((unsigned long long)key << 32)
                                      | (unsigned long long)(~idx);
                    }
                }
            }
            __syncthreads();
            Mc = s_cnt;
        } else {
            // level-2 refine within bin b1 on bits [20:10]
            for (int i = tid; i < NBINS; i += RTHREADS) s_hist[i] = 0;
            __syncthreads();
            for (int i = tid; i < NV4; i += RTHREADS) {
                float4 v = lg4[i];
                float vv[4] = {v.x, v.y, v.z, v.w};
                #pragma unroll
                for (int j = 0; j < 4; j++) {
                    unsigned key = f2key(vv[j]);
                    if ((int)(key >> 21) == b1)
                        atomicAdd(&s_hist[(key >> 10) & 0x7FFu], 1u);
                }
            }
            __syncthreads();
            if (tid == 0) {
                int need = KTOP - s_gt;
                int acc = 0, b2 = 0;
                for (int bin = NBINS - 1; bin >= 0; bin--) {
                    int c = (int)s_hist[bin];
                    if (acc + c >= need) { b2 = bin; break; }
                    acc += c;
                }
                s_b2 = b2; s_cnt = 0;
            }
            __syncthreads();
            const int b2 = s_b2;
            for (int i = tid; i < NV4; i += RTHREADS) {
                float4 v = lg4[i];
                float vv[4] = {v.x, v.y, v.z, v.w};
                #pragma unroll
                for (int j = 0; j < 4; j++) {
                    unsigned key = f2key(vv[j]);
                    int hb = (int)(key >> 21);
                    bool take = (hb > b1) ||
                                (hb == b1 && (int)((key >> 10) & 0x7FFu) >= b2);
                    if (take) {
                        int pos = atomicAdd(&s_cnt, 1);
                        if (pos < CAP) {
                            unsigned idx = (unsigned)(i * 4 + j);
                            s_pack[pos] = ((unsigned long long)key << 32)
                                          | (unsigned long long)(~idx);
                        }
                    }
                }
            }
            __syncthreads();
            Mc = min(s_cnt, CAP);
        }
    }

    // ---------- Exact ranking (descending key, lower idx first on ties) ----------
    for (int i = tid; i < Mc; i += RTHREADS) {
        unsigned long long pi = s_pack[i];
        int r = 0;
        for (int j = 0; j < Mc; j++)
            r += (s_pack[j] > pi);
        if (r < KTOP) {
            unsigned key = (unsigned)(pi >> 32);
            unsigned idx = ~(unsigned)(pi & 0xFFFFFFFFull);
            int q = (int)(idx / CC);
            int c = (int)(idx % CC);
            float lv = key2f(key);
            float score = 1.0f / (1.0f + expf(-lv));

            size_t slot = (size_t)b * KTOP + r;
            out[LBL_OFF + slot] = (float)c;
            out[SCR_OFF + slot] = score;

            float4 bx = ((const float4*)boxes)[(size_t)b * QQ + q];
            float4 o;
            o.x = bx.x - 0.5f * bx.z;
            o.y = bx.y - 0.5f * bx.w;
            o.z = bx.x + 0.5f * bx.z;
            o.w = bx.y + 0.5f * bx.w;
            ((float4*)(out + BOX_OFF))[slot] = o;
        }
    }
}

extern "C" void kernel_launch(void* const* d_in, const int* in_sizes, int n_in,
                              void* d_out, int out_size)
{
    const float* logits = (const float*)d_in[0];
    const float* boxes  = (const float*)d_in[1];
    float* out = (float*)d_out;

    dim3 fgrid(BPB, BATCH);
    filter_kernel<<<fgrid, FTHREADS>>>(logits);
    rank_kernel<<<BATCH, RTHREADS>>>(logits, boxes, out);
}

// round 7
// speedup vs baseline: 2.3993x; 2.3993x over previous
#include <cuda_runtime.h>
#include <cstdint>

// DETR-style postprocess:
//   logits [256,1000,80] f32, boxes [256,1000,4] f32 (cxcywh)
//   -> labels [256,300], boxes_xyxy [256,300,4], scores [256,300]
// Output concatenated flat f32: labels | boxes | scores. (verified R3)

#define BATCH      256
#define QQ         1000
#define CC         80
#define NELEM      80000      // QQ*CC per batch
#define NV4        20000      // NELEM/4
#define KTOP       300
#define CAP        4096
#define NBINS      2048       // 11-bit radix level
#define NTHREADS   1024
#define T_STATIC   2.5f

#define LBL_OFF    0
#define BOX_OFF    (BATCH * KTOP)            // 76800
#define SCR_OFF    (BATCH * KTOP * 5)        // 384000

// Monotone float->uint key (ascending order preserved)
__device__ __forceinline__ unsigned f2key(float x) {
    unsigned b = __float_as_uint(x);
    return (b & 0x80000000u) ? ~b : (b | 0x80000000u);
}
__device__ __forceinline__ float key2f(unsigned k) {
    unsigned b = (k & 0x80000000u) ? (k & 0x7FFFFFFFu) : ~k;
    return __uint_as_float(b);
}

__global__ __launch_bounds__(NTHREADS, 2)
void postproc_topk_kernel(const float* __restrict__ logits,
                          const float* __restrict__ boxes,
                          float* __restrict__ out)
{
    __shared__ unsigned long long s_pack[CAP];   // (key<<32) | ~idx
    __shared__ unsigned s_hist[NBINS];           // fallback only
    __shared__ int s_cnt;
    __shared__ int s_b1, s_gt, s_b2;

    const int b   = blockIdx.x;
    const int tid = threadIdx.x;
    const float4* lg4 = (const float4*)(logits + (size_t)b * NELEM);

    if (tid == 0) s_cnt = 0;
    __syncthreads();

    // ---------- Primary path: single streaming pass, static threshold ----------
    for (int i = tid; i < NV4; i += NTHREADS) {
        float4 v = lg4[i];
        float vv[4] = {v.x, v.y, v.z, v.w};
        #pragma unroll
        for (int j = 0; j < 4; j++) {
            if (vv[j] > T_STATIC) {
                int pos = atomicAdd(&s_cnt, 1);
                if (pos < CAP) {
                    unsigned idx = (unsigned)(i * 4 + j);
                    s_pack[pos] = ((unsigned long long)f2key(vv[j]) << 32)
                                  | (unsigned long long)(~idx);
                }
            }
        }
    }
    __syncthreads();
    int M = s_cnt;

    // ---------- Fallback: exact 2-level radix select (statistically never) ----------
    if (M < KTOP || M > CAP) {
        // level-1 histogram on top 11 bits of key
        for (int i = tid; i < NBINS; i += NTHREADS) s_hist[i] = 0;
        __syncthreads();
        for (int i = tid; i < NV4; i += NTHREADS) {
            float4 v = lg4[i];
            float vv[4] = {v.x, v.y, v.z, v.w};
            #pragma unroll
            for (int j = 0; j < 4; j++)
                atomicAdd(&s_hist[f2key(vv[j]) >> 21], 1u);
        }
        __syncthreads();
        if (tid == 0) {
            int acc = 0, b1 = 0;
            for (int bin = NBINS - 1; bin >= 0; bin--) {
                int c = (int)s_hist[bin];
                if (acc + c >= KTOP) { b1 = bin; break; }
                acc += c;
            }
            s_b1 = b1; s_gt = acc;
        }
        __syncthreads();
        const int b1 = s_b1;
        const int cnt_ge = s_gt + (int)s_hist[b1];

        if (cnt_ge <= CAP) {
            if (tid == 0) s_cnt = 0;
            __syncthreads();
            for (int i = tid; i < NV4; i += NTHREADS) {
                float4 v = lg4[i];
                float vv[4] = {v.x, v.y, v.z, v.w};
                #pragma unroll
                for (int j = 0; j < 4; j++) {
                    unsigned key = f2key(vv[j]);
                    if ((int)(key >> 21) >= b1) {
                        int pos = atomicAdd(&s_cnt, 1);
                        unsigned idx = (unsigned)(i * 4 + j);
                        s_pack[pos] = ((unsigned long long)key << 32)
                                      | (unsigned long long)(~idx);
                    }
                }
            }
            __syncthreads();
            M = s_cnt;
        } else {
            // level-2 refine within bin b1 on bits [20:10]
            for (int i = tid; i < NBINS; i += NTHREADS) s_hist[i] = 0;
            __syncthreads();
            for (int i = tid; i < NV4; i += NTHREADS) {
                float4 v = lg4[i];
                float vv[4] = {v.x, v.y, v.z, v.w};
                #pragma unroll
                for (int j = 0; j < 4; j++) {
                    unsigned key = f2key(vv[j]);
                    if ((int)(key >> 21) == b1)
                        atomicAdd(&s_hist[(key >> 10) & 0x7FFu], 1u);
                }
            }
            __syncthreads();
            if (tid == 0) {
                int need = KTOP - s_gt;
                int acc = 0, b2 = 0;
                for (int bin = NBINS - 1; bin >= 0; bin--) {
                    int c = (int)s_hist[bin];
                    if (acc + c >= need) { b2 = bin; break; }
                    acc += c;
                }
                s_b2 = b2; s_cnt = 0;
            }
            __syncthreads();
            const int b2 = s_b2;
            for (int i = tid; i < NV4; i += NTHREADS) {
                float4 v = lg4[i];
                float vv[4] = {v.x, v.y, v.z, v.w};
                #pragma unroll
                for (int j = 0; j < 4; j++) {
                    unsigned key = f2key(vv[j]);
                    int hb = (int)(key >> 21);
                    bool take = (hb > b1) ||
                                (hb == b1 && (int)((key >> 10) & 0x7FFu) >= b2);
                    if (take) {
                        int pos = atomicAdd(&s_cnt, 1);
                        if (pos < CAP) {
                            unsigned idx = (unsigned)(i * 4 + j);
                            s_pack[pos] = ((unsigned long long)key << 32)
                                          | (unsigned long long)(~idx);
                        }
                    }
                }
            }
            __syncthreads();
            M = min(s_cnt, CAP);
        }
    }

    // ---------- Exact ranking (descending key, lower idx first on ties) ----------
    // pack = (key<<32)|~idx => larger pack == earlier in top-k order; all packs
    // distinct (distinct idx), so ranks form a permutation 0..M-1.
    for (int i = tid; i < M; i += NTHREADS) {
        unsigned long long pi = s_pack[i];
        int r = 0;
        for (int j = 0; j < M; j++)
            r += (s_pack[j] > pi);
        if (r < KTOP) {
            unsigned key = (unsigned)(pi >> 32);
            unsigned idx = ~(unsigned)(pi & 0xFFFFFFFFull);
            int q = (int)(idx / CC);
            int c = (int)(idx % CC);
            float lv = key2f(key);
            float score = 1.0f / (1.0f + expf(-lv));

            size_t slot = (size_t)b * KTOP + r;
            out[LBL_OFF + slot] = (float)c;
            out[SCR_OFF + slot] = score;

            float4 bx = ((const float4*)boxes)[(size_t)b * QQ + q];
            float4 o;
            o.x = bx.x - 0.5f * bx.z;
            o.y = bx.y - 0.5f * bx.w;
            o.z = bx.x + 0.5f * bx.z;
            o.w = bx.y + 0.5f * bx.w;
            ((float4*)(out + BOX_OFF))[slot] = o;
        }
    }
}

extern "C" void kernel_launch(void* const* d_in, const int* in_sizes, int n_in,
                              void* d_out, int out_size)
{
    const float* logits = (const float*)d_in[0];
    const float* boxes  = (const float*)d_in[1];
    float* out = (float*)d_out;
    postproc_topk_kernel<<<BATCH, NTHREADS>>>(logits, boxes, out);
}

// round 8
// speedup vs baseline: 2.5436x; 1.0601x over previous
#include <cuda_runtime.h>
#include <cstdint>

// DETR-style postprocess:
//   logits [256,1000,80] f32, boxes [256,1000,4] f32 (cxcywh)
//   -> labels [256,300], boxes_xyxy [256,300,4], scores [256,300]
// Output concatenated flat f32: labels | boxes | scores. (verified R3)

#define BATCH      256
#define QQ         1000
#define CC         80
#define NELEM      80000      // QQ*CC per batch
#define NV4        20000      // NELEM/4
#define KTOP       300
#define CAP        4096
#define NBINS      2048       // 11-bit radix level
#define NTHREADS   1024
#define T_STATIC   2.5f

#define LBL_OFF    0
#define BOX_OFF    (BATCH * KTOP)            // 76800
#define SCR_OFF    (BATCH * KTOP * 5)        // 384000

// Monotone float->uint key (ascending order preserved)
__device__ __forceinline__ unsigned f2key(float x) {
    unsigned b = __float_as_uint(x);
    return (b & 0x80000000u) ? ~b : (b | 0x80000000u);
}
__device__ __forceinline__ float key2f(unsigned k) {
    unsigned b = (k & 0x80000000u) ? (k & 0x7FFFFFFFu) : ~k;
    return __uint_as_float(b);
}

__global__ __launch_bounds__(NTHREADS, 2)
void postproc_topk_kernel(const float* __restrict__ logits,
                          const float* __restrict__ boxes,
                          float* __restrict__ out)
{
    __shared__ __align__(16) unsigned long long s_pack[CAP];  // (key<<32) | ~idx
    __shared__ unsigned s_hist[NBINS];                         // fallback only
    __shared__ int s_cnt;
    __shared__ int s_b1, s_gt, s_b2;

    const int b   = blockIdx.x;
    const int tid = threadIdx.x;
    const float4* lg4 = (const float4*)(logits + (size_t)b * NELEM);

    if (tid == 0) s_cnt = 0;
    __syncthreads();

    // ---------- Primary path: streaming pass, MLP=4, static threshold ----------
    // 20000 float4 = 4 full tiles of 4096 + tail tile (3616).
    #pragma unroll 1
    for (int it = 0; it < 4; it++) {
        int base = it * 4096 + tid;
        // 4 independent loads, one base reg + immediate offsets -> front-batched
        float4 v0 = lg4[base];
        float4 v1 = lg4[base + 1024];
        float4 v2 = lg4[base + 2048];
        float4 v3 = lg4[base + 3072];

        float vv[16] = {v0.x, v0.y, v0.z, v0.w,  v1.x, v1.y, v1.z, v1.w,
                        v2.x, v2.y, v2.z, v2.w,  v3.x, v3.y, v3.z, v3.w};
        #pragma unroll
        for (int k = 0; k < 16; k++) {
            if (vv[k] > T_STATIC) {
                int pos = atomicAdd(&s_cnt, 1);
                if (pos < CAP) {
                    unsigned idx = (unsigned)((base + (k >> 2) * 1024) * 4 + (k & 3));
                    s_pack[pos] = ((unsigned long long)f2key(vv[k]) << 32)
                                  | (unsigned long long)(~idx);
                }
            }
        }
    }
    {   // tail tile: base in [16384, 20479]; only 4th load can go OOB (tid>=544)
        int base = 16384 + tid;
        float4 v0 = lg4[base];
        float4 v1 = lg4[base + 1024];
        float4 v2 = lg4[base + 2048];
        float4 v3 = make_float4(-1e30f, -1e30f, -1e30f, -1e30f);
        if (tid < 544) v3 = lg4[base + 3072];

        float vv[16] = {v0.x, v0.y, v0.z, v0.w,  v1.x, v1.y, v1.z, v1.w,
                        v2.x, v2.y, v2.z, v2.w,  v3.x, v3.y, v3.z, v3.w};
        #pragma unroll
        for (int k = 0; k < 16; k++) {
            if (vv[k] > T_STATIC) {
                int pos = atomicAdd(&s_cnt, 1);
                if (pos < CAP) {
                    unsigned idx = (unsigned)((base + (k >> 2) * 1024) * 4 + (k & 3));
                    s_pack[pos] = ((unsigned long long)f2key(vv[k]) << 32)
                                  | (unsigned long long)(~idx);
                }
            }
        }
    }
    __syncthreads();
    int M = s_cnt;

    // ---------- Fallback: exact 2-level radix select (statistically never) ----------
    if (M < KTOP || M > CAP) {
        for (int i = tid; i < NBINS; i += NTHREADS) s_hist[i] = 0;
        __syncthreads();
        for (int i = tid; i < NV4; i += NTHREADS) {
            float4 v = lg4[i];
            float vv[4] = {v.x, v.y, v.z, v.w};
            #pragma unroll
            for (int j = 0; j < 4; j++)
                atomicAdd(&s_hist[f2key(vv[j]) >> 21], 1u);
        }
        __syncthreads();
        if (tid == 0) {
            int acc = 0, b1 = 0;
            for (int bin = NBINS - 1; bin >= 0; bin--) {
                int c = (int)s_hist[bin];
                if (acc + c >= KTOP) { b1 = bin; break; }
                acc += c;
            }
            s_b1 = b1; s_gt = acc;
        }
        __syncthreads();
        const int b1 = s_b1;
        const int cnt_ge = s_gt + (int)s_hist[b1];

        if (cnt_ge <= CAP) {
            if (tid == 0) s_cnt = 0;
            __syncthreads();
            for (int i = tid; i < NV4; i += NTHREADS) {
                float4 v = lg4[i];
                float vv[4] = {v.x, v.y, v.z, v.w};
                #pragma unroll
                for (int j = 0; j < 4; j++) {
                    unsigned key = f2key(vv[j]);
                    if ((int)(key >> 21) >= b1) {
                        int pos = atomicAdd(&s_cnt, 1);
                        unsigned idx = (unsigned)(i * 4 + j);
                        s_pack[pos] = ((unsigned long long)key << 32)
                                      | (unsigned long long)(~idx);
                    }
                }
            }
            __syncthreads();
            M = s_cnt;
        } else {
            for (int i = tid; i < NBINS; i += NTHREADS) s_hist[i] = 0;
            __syncthreads();
            for (int i = tid; i < NV4; i += NTHREADS) {
                float4 v = lg4[i];
                float vv[4] = {v.x, v.y, v.z, v.w};
                #pragma unroll
                for (int j = 0; j < 4; j++) {
                    unsigned key = f2key(vv[j]);
                    if ((int)(key >> 21) == b1)
                        atomicAdd(&s_hist[(key >> 10) & 0x7FFu], 1u);
                }
            }
            __syncthreads();
            if (tid == 0) {
                int need = KTOP - s_gt;
                int acc = 0, b2 = 0;
                for (int bin = NBINS - 1; bin >= 0; bin--) {
                    int c = (int)s_hist[bin];
                    if (acc + c >= need) { b2 = bin; break; }
                    acc += c;
                }
                s_b2 = b2; s_cnt = 0;
            }
            __syncthreads();
            const int b2 = s_b2;
            for (int i = tid; i < NV4; i += NTHREADS) {
                float4 v = lg4[i];
                float vv[4] = {v.x, v.y, v.z, v.w};
                #pragma unroll
                for (int j = 0; j < 4; j++) {
                    unsigned key = f2key(vv[j]);
                    int hb = (int)(key >> 21);
                    bool take = (hb > b1) ||
                                (hb == b1 && (int)((key >> 10) & 0x7FFu) >= b2);
                    if (take) {
                        int pos = atomicAdd(&s_cnt, 1);
                        if (pos < CAP) {
                            unsigned idx = (unsigned)(i * 4 + j);
                            s_pack[pos] = ((unsigned long long)key << 32)
                                          | (unsigned long long)(~idx);
                        }
                    }
                }
            }
            __syncthreads();
            M = min(s_cnt, CAP);
        }
    }

    // pad one zero key so the paired inner loop can read an even count
    // (zero pack is smaller than every real pack -> never counted)
    if (tid == 0 && M < CAP) s_pack[M] = 0ULL;
    __syncthreads();
    const int Mpair = (M + 1) >> 1;
    const ulonglong2* sp2 = (const ulonglong2*)s_pack;

    // ---------- Exact ranking (descending key, lower idx first on ties) ----------
    for (int i = tid; i < M; i += NTHREADS) {
        unsigned long long pi = s_pack[i];
        int r = 0;
        for (int j = 0; j < Mpair; j++) {
            ulonglong2 pj = sp2[j];
            r += (pj.x > pi) + (pj.y > pi);
        }
        if (r < KTOP) {
            unsigned key = (unsigned)(pi >> 32);
            unsigned idx = ~(unsigned)(pi & 0xFFFFFFFFull);
            int q = (int)(idx / CC);
            int c = (int)(idx % CC);
            float lv = key2f(key);
            float score = 1.0f / (1.0f + expf(-lv));

            size_t slot = (size_t)b * KTOP + r;
            out[LBL_OFF + slot] = (float)c;
            out[SCR_OFF + slot] = score;

            float4 bx = ((const float4*)boxes)[(size_t)b * QQ + q];
            float4 o;
            o.x = bx.x - 0.5f * bx.z;
            o.y = bx.y - 0.5f * bx.w;
            o.z = bx.x + 0.5f * bx.z;
            o.w = bx.y + 0.5f * bx.w;
            ((float4*)(out + BOX_OFF))[slot] = o;
        }
    }
}

extern "C" void kernel_launch(void* const* d_in, const int* in_sizes, int n_in,
                              void* d_out, int out_size)
{
    const float* logits = (const float*)d_in[0];
    const float* boxes  = (const float*)d_in[1];
    float* out = (float*)d_out;
    postproc_topk_kernel<<<BATCH, NTHREADS>>>(logits, boxes, out);
}